// round 1
// baseline (speedup 1.0000x reference)
#include <cuda_runtime.h>
#include <cstdint>

#define B_    2048
#define N_    32
#define F_    64
#define E_    8
#define H_    128
#define NA_   4
#define NACT_ 16
#define K_TOT 585   // 512 (We@Wrel) + 64 (We@Wroot) + 8 (mask: be@Wrel) + 1 (bias)

// Folded weight matrix [K_TOT x H] — scratch (no allocations allowed)
__device__ float g_Wcat[K_TOT * H_];

// ---------------------------------------------------------------------------
// Kernel A: fold We/be into Wrel/Wroot/brel.  grid=585, block=128. ~19 MF.
// ---------------------------------------------------------------------------
__global__ void precompute_wcat(const float* __restrict__ We,
                                const float* __restrict__ be,
                                const float* __restrict__ Wrel,
                                const float* __restrict__ Wroot,
                                const float* __restrict__ brel) {
    __shared__ float vec[H_];
    const int r = blockIdx.x;
    const int h = threadIdx.x;
    const float* Bmat;
    float addv = 0.0f;
    if (r < 512) {                     // (We @ Wrel[e])[d,:]
        int e = r >> 6, d = r & 63;
        vec[h] = We[d * H_ + h];
        Bmat = Wrel + e * H_ * H_;
    } else if (r < 576) {              // (We @ Wroot)[d,:]
        int d = r - 512;
        vec[h] = We[d * H_ + h];
        Bmat = Wroot;
    } else if (r < 584) {              // be @ Wrel[e]
        int e = r - 576;
        vec[h] = be[h];
        Bmat = Wrel + e * H_ * H_;
    } else {                           // brel + be @ Wroot
        vec[h] = be[h];
        Bmat = Wroot;
        addv = brel[h];
    }
    __syncthreads();
    float acc = addv;
    #pragma unroll 8
    for (int t = 0; t < H_; ++t)
        acc = fmaf(vec[t], __ldg(Bmat + t * H_ + h), acc);
    g_Wcat[r * H_ + h] = acc;
}

// ---------------------------------------------------------------------------
// Kernel B: fully fused main kernel. One block per batch element.
// ---------------------------------------------------------------------------
struct SmemB {
    float    u[N_][F_ + 1];      // unary[b], padded (bank-conflict-free row reads)
    unsigned m[E_ * N_];         // adjacency bitmasks: m[e*32+j] bit i = A[b,e,i,j]
    float    cinv[E_ * N_];      // deg>0 ? 1/deg : 0
    float    ubarT[256][N_];     // aggregated-u chunk, transposed [k_local][j]
    float    wtile[64][H_];      // staged Wcat k-tile
    float    pooled[H_];
    float    zs[NA_][H_];
    int      cols[NA_];
};

__global__ __launch_bounds__(256, 2) void critic_main(
    const float* __restrict__ unary,    // [B,N,F]
    const int*   __restrict__ binary,   // [B,N,N,E]
    const float* __restrict__ actions,  // [NA,B,NACT]
    const float* __restrict__ W1,       // [NA,H,H]
    const float* __restrict__ b1,       // [NA,H]
    const float* __restrict__ W2,       // [NA,H,NACT]
    const float* __restrict__ b2,       // [NA,NACT]
    float* __restrict__ qout)           // [NA,B,1]
{
    extern __shared__ char smem_raw[];
    SmemB& s = *reinterpret_cast<SmemB*>(smem_raw);

    const int tid  = threadIdx.x;
    const int b    = blockIdx.x;
    const int lane = tid & 31;   // = node j in GEMM
    const int w    = tid >> 5;   // warp = 16-column group

    // ---- load u[b] (2048 floats, coalesced) ----
    const float* ub = unary + (size_t)b * (N_ * F_);
    #pragma unroll
    for (int p = 0; p < 8; ++p) {
        int li = tid + p * 256;
        s.u[li >> 6][li & 63] = ub[li];
    }
    s.m[tid] = 0u;
    __syncthreads();

    // ---- binary[b] (8192 ints, int4-coalesced) -> bitmasks ----
    const int4* bb = reinterpret_cast<const int4*>(binary + (size_t)b * (N_ * N_ * E_));
    #pragma unroll
    for (int p = 0; p < 8; ++p) {
        int q4 = tid + p * 256;
        int4 v = bb[q4];
        int l  = q4 * 4;              // linear index (i*32 + j)*8 + e
        int i  = l >> 8;
        int j  = (l >> 3) & 31;
        int e0 = l & 7;               // 0 or 4
        unsigned bit = 1u << i;
        if (v.x) atomicOr(&s.m[(e0 + 0) * 32 + j], bit);
        if (v.y) atomicOr(&s.m[(e0 + 1) * 32 + j], bit);
        if (v.z) atomicOr(&s.m[(e0 + 2) * 32 + j], bit);
        if (v.w) atomicOr(&s.m[(e0 + 3) * 32 + j], bit);
    }
    __syncthreads();
    {
        int d = __popc(s.m[tid]);
        s.cinv[tid] = d ? (1.0f / (float)d) : 0.0f;
    }

    // ---- h[j][w*16+c] accumulators ----
    float acc[16];
    #pragma unroll
    for (int c = 0; c < 16; ++c) acc[c] = 0.0f;

    // ---- 2 chunks of 4 relations: aggregate then GEMM (K=256 each) ----
    for (int chunk = 0; chunk < 2; ++chunk) {
        __syncthreads();   // cinv ready (1st iter) / prior GEMM done reading ubarT
        {
            // thread -> (e_local, d-half, j); warp-uniform (e,dh) => u reads broadcast
            int e_l = tid >> 6;
            int dh  = (tid >> 5) & 1;
            int j   = tid & 31;
            int ei  = chunk * 4 + e_l;
            unsigned msk = s.m[ei * 32 + j];
            float    ci  = s.cinv[ei * 32 + j];
            float a2[32];
            #pragma unroll
            for (int d = 0; d < 32; ++d) a2[d] = 0.0f;
            int dbase = dh * 32;
            #pragma unroll
            for (int i = 0; i < 32; ++i) {
                float f = ((msk >> i) & 1u) ? 1.0f : 0.0f;
                const float* ur = &s.u[i][dbase];
                #pragma unroll
                for (int d = 0; d < 32; ++d)
                    a2[d] = fmaf(f, ur[d], a2[d]);
            }
            int rbase = e_l * 64 + dbase;
            #pragma unroll
            for (int d = 0; d < 32; ++d)
                s.ubarT[rbase + d][j] = a2[d] * ci;   // bank = j: conflict-free
        }
        __syncthreads();

        for (int kt = 0; kt < 4; ++kt) {
            // stage 64-row Wcat tile (coalesced float4)
            int row0 = chunk * 256 + kt * 64;
            {
                const float4* src = reinterpret_cast<const float4*>(g_Wcat + row0 * H_);
                float4*       dst = reinterpret_cast<float4*>(&s.wtile[0][0]);
                #pragma unroll
                for (int p = 0; p < 8; ++p)
                    dst[tid + p * 256] = src[tid + p * 256];
            }
            __syncthreads();
            #pragma unroll 4
            for (int k = 0; k < 64; ++k) {
                float a = s.ubarT[kt * 64 + k][lane];
                const float4* wr = reinterpret_cast<const float4*>(&s.wtile[k][w * 16]);
                float4 w0 = wr[0], w1 = wr[1], w2 = wr[2], w3 = wr[3];
                acc[0]  = fmaf(a, w0.x, acc[0]);  acc[1]  = fmaf(a, w0.y, acc[1]);
                acc[2]  = fmaf(a, w0.z, acc[2]);  acc[3]  = fmaf(a, w0.w, acc[3]);
                acc[4]  = fmaf(a, w1.x, acc[4]);  acc[5]  = fmaf(a, w1.y, acc[5]);
                acc[6]  = fmaf(a, w1.z, acc[6]);  acc[7]  = fmaf(a, w1.w, acc[7]);
                acc[8]  = fmaf(a, w2.x, acc[8]);  acc[9]  = fmaf(a, w2.y, acc[9]);
                acc[10] = fmaf(a, w2.z, acc[10]); acc[11] = fmaf(a, w2.w, acc[11]);
                acc[12] = fmaf(a, w3.x, acc[12]); acc[13] = fmaf(a, w3.y, acc[13]);
                acc[14] = fmaf(a, w3.z, acc[14]); acc[15] = fmaf(a, w3.w, acc[15]);
            }
            __syncthreads();   // before next tile overwrite
        }
    }

    // ---- root term: rows 512..575, activation = u[j][d] ----
    {
        const float4* src = reinterpret_cast<const float4*>(g_Wcat + 512 * H_);
        float4*       dst = reinterpret_cast<float4*>(&s.wtile[0][0]);
        #pragma unroll
        for (int p = 0; p < 8; ++p)
            dst[tid + p * 256] = src[tid + p * 256];
    }
    __syncthreads();
    #pragma unroll 4
    for (int d = 0; d < 64; ++d) {
        float a = s.u[lane][d];   // padded stride 65 -> conflict-free
        const float4* wr = reinterpret_cast<const float4*>(&s.wtile[d][w * 16]);
        float4 w0 = wr[0], w1 = wr[1], w2 = wr[2], w3 = wr[3];
        acc[0]  = fmaf(a, w0.x, acc[0]);  acc[1]  = fmaf(a, w0.y, acc[1]);
        acc[2]  = fmaf(a, w0.z, acc[2]);  acc[3]  = fmaf(a, w0.w, acc[3]);
        acc[4]  = fmaf(a, w1.x, acc[4]);  acc[5]  = fmaf(a, w1.y, acc[5]);
        acc[6]  = fmaf(a, w1.z, acc[6]);  acc[7]  = fmaf(a, w1.w, acc[7]);
        acc[8]  = fmaf(a, w2.x, acc[8]);  acc[9]  = fmaf(a, w2.y, acc[9]);
        acc[10] = fmaf(a, w2.z, acc[10]); acc[11] = fmaf(a, w2.w, acc[11]);
        acc[12] = fmaf(a, w3.x, acc[12]); acc[13] = fmaf(a, w3.y, acc[13]);
        acc[14] = fmaf(a, w3.z, acc[14]); acc[15] = fmaf(a, w3.w, acc[15]);
    }

    // ---- mask bias (rows 576..583) + constant bias (row 584), direct L2 ----
    #pragma unroll
    for (int e = 0; e < E_; ++e) {
        float a = s.m[e * 32 + lane] ? 1.0f : 0.0f;
        const float4* wr = reinterpret_cast<const float4*>(g_Wcat + (576 + e) * H_ + w * 16);
        float4 w0 = __ldg(wr), w1 = __ldg(wr + 1), w2 = __ldg(wr + 2), w3 = __ldg(wr + 3);
        acc[0]  = fmaf(a, w0.x, acc[0]);  acc[1]  = fmaf(a, w0.y, acc[1]);
        acc[2]  = fmaf(a, w0.z, acc[2]);  acc[3]  = fmaf(a, w0.w, acc[3]);
        acc[4]  = fmaf(a, w1.x, acc[4]);  acc[5]  = fmaf(a, w1.y, acc[5]);
        acc[6]  = fmaf(a, w1.z, acc[6]);  acc[7]  = fmaf(a, w1.w, acc[7]);
        acc[8]  = fmaf(a, w2.x, acc[8]);  acc[9]  = fmaf(a, w2.y, acc[9]);
        acc[10] = fmaf(a, w2.z, acc[10]); acc[11] = fmaf(a, w2.w, acc[11]);
        acc[12] = fmaf(a, w3.x, acc[12]); acc[13] = fmaf(a, w3.y, acc[13]);
        acc[14] = fmaf(a, w3.z, acc[14]); acc[15] = fmaf(a, w3.w, acc[15]);
    }
    {
        const float4* wr = reinterpret_cast<const float4*>(g_Wcat + 584 * H_ + w * 16);
        float4 w0 = __ldg(wr), w1 = __ldg(wr + 1), w2 = __ldg(wr + 2), w3 = __ldg(wr + 3);
        acc[0]  += w0.x; acc[1]  += w0.y; acc[2]  += w0.z; acc[3]  += w0.w;
        acc[4]  += w1.x; acc[5]  += w1.y; acc[6]  += w1.z; acc[7]  += w1.w;
        acc[8]  += w2.x; acc[9]  += w2.y; acc[10] += w2.z; acc[11] += w2.w;
        acc[12] += w3.x; acc[13] += w3.y; acc[14] += w3.z; acc[15] += w3.w;
    }

    // ---- relu + max-pool over nodes (lanes) ----
    #pragma unroll
    for (int c = 0; c < 16; ++c) {
        float v = fmaxf(acc[c], 0.0f);
        #pragma unroll
        for (int off = 16; off; off >>= 1)
            v = fmaxf(v, __shfl_xor_sync(0xffffffffu, v, off));
        if (lane == 0) s.pooled[w * 16 + c] = v;
    }
    __syncthreads();

    // ---- per-agent heads: z = leaky(pooled@W1 + b1); q = z@W2[:,argmax] + b2 ----
    if (tid < NA_) {
        const float* ap = actions + ((size_t)tid * B_ + b) * NACT_;
        float best = ap[0]; int col = 0;
        #pragma unroll
        for (int k = 1; k < NACT_; ++k) {
            float v = ap[k];
            if (v > best) { best = v; col = k; }
        }
        s.cols[tid] = col;
    }
    {
        int a  = tid >> 6;       // agent
        int hh = tid & 63;
        #pragma unroll
        for (int rep = 0; rep < 2; ++rep) {
            int h = hh + rep * 64;
            float z = b1[a * H_ + h];
            const float* w1p = W1 + a * H_ * H_ + h;
            #pragma unroll 8
            for (int t = 0; t < H_; ++t)
                z = fmaf(s.pooled[t], __ldg(w1p + t * H_), z);
            z = (z > 0.0f) ? z : 0.01f * z;   // LeakyReLU
            s.zs[a][h] = z;
        }
    }
    __syncthreads();
    if (tid < NA_) {
        int a = tid;
        int col = s.cols[a];
        float q = b2[a * NACT_ + col];
        const float* w2p = W2 + a * H_ * NACT_ + col;
        #pragma unroll 8
        for (int h = 0; h < H_; ++h)
            q = fmaf(s.zs[a][h], __ldg(w2p + h * NACT_), q);
        qout[(size_t)a * B_ + b] = q;
    }
}

// ---------------------------------------------------------------------------
extern "C" void kernel_launch(void* const* d_in, const int* in_sizes, int n_in,
                              void* d_out, int out_size) {
    const float* unary   = (const float*)d_in[0];
    const int*   binary  = (const int*)  d_in[1];
    const float* actions = (const float*)d_in[2];
    const float* We      = (const float*)d_in[3];
    const float* be      = (const float*)d_in[4];
    const float* Wrel    = (const float*)d_in[5];
    const float* Wroot   = (const float*)d_in[6];
    const float* brel    = (const float*)d_in[7];
    const float* W1      = (const float*)d_in[8];
    const float* b1      = (const float*)d_in[9];
    const float* W2      = (const float*)d_in[10];
    const float* b2      = (const float*)d_in[11];
    float* qout = (float*)d_out;

    cudaFuncSetAttribute(critic_main, cudaFuncAttributeMaxDynamicSharedMemorySize,
                         (int)sizeof(SmemB));

    precompute_wcat<<<K_TOT, H_>>>(We, be, Wrel, Wroot, brel);
    critic_main<<<B_, 256, sizeof(SmemB)>>>(unary, binary, actions, W1, b1, W2, b2, qout);
}

// round 3
// speedup vs baseline: 1.3281x; 1.3281x over previous
#include <cuda_runtime.h>
#include <cstdint>

#define B_    2048
#define N_    32
#define F_    64
#define E_    8
#define H_    128
#define NA_   4
#define NACT_ 16
#define K_TOT 585   // 512 (We@Wrel) + 64 (We@Wroot) + 8 (mask: be@Wrel) + 1 (bias)
#define K_MAIN 576  // rows handled by the uniform GEMM loop (9 tiles of 64)

// Folded weight matrix [K_TOT x H] — scratch (no allocations allowed)
__device__ float g_Wcat[K_TOT * H_];

// ---------------------------------------------------------------------------
// Kernel A: fold We/be into Wrel/Wroot/brel.  grid=585, block=128. ~19 MF.
// ---------------------------------------------------------------------------
__global__ void precompute_wcat(const float* __restrict__ We,
                                const float* __restrict__ be,
                                const float* __restrict__ Wrel,
                                const float* __restrict__ Wroot,
                                const float* __restrict__ brel) {
    __shared__ float vec[H_];
    const int r = blockIdx.x;
    const int h = threadIdx.x;
    const float* Bmat;
    float addv = 0.0f;
    if (r < 512) {                     // (We @ Wrel[e])[d,:]
        int e = r >> 6, d = r & 63;
        vec[h] = We[d * H_ + h];
        Bmat = Wrel + e * H_ * H_;
    } else if (r < 576) {              // (We @ Wroot)[d,:]
        int d = r - 512;
        vec[h] = We[d * H_ + h];
        Bmat = Wroot;
    } else if (r < 584) {              // be @ Wrel[e]
        int e = r - 576;
        vec[h] = be[h];
        Bmat = Wrel + e * H_ * H_;
    } else {                           // brel + be @ Wroot
        vec[h] = be[h];
        Bmat = Wroot;
        addv = brel[h];
    }
    __syncthreads();
    float acc = addv;
    #pragma unroll 8
    for (int t = 0; t < H_; ++t)
        acc = fmaf(vec[t], __ldg(Bmat + t * H_ + h), acc);
    g_Wcat[r * H_ + h] = acc;
}

// ---------------------------------------------------------------------------
// Kernel B: fully fused main kernel. One block per batch element.
// ---------------------------------------------------------------------------
struct SmemB {
    float ubarT[K_MAIN][N_];        // 73728 B: activation rows (agg + root), [k][j]
    union Ov {
        struct {
            float u[N_][F_];        // unary[b], UNPADDED (16B-aligned float4 rows)
            float cinv[E_ * N_];
        } p1;
        float wtile[64][H_];        // staged Wcat k-tile (GEMM phase)
    } ov;
    unsigned m[E_ * N_];            // bitmasks: m[e*32+j] bit i = A[b,e,i,j]
    float    pooled[H_];
    float    zs[NA_][H_];
    int      cols[NA_];
};

__global__ __launch_bounds__(256, 2) void critic_main(
    const float* __restrict__ unary,    // [B,N,F]
    const int*   __restrict__ binary,   // [B,N,N,E]
    const float* __restrict__ actions,  // [NA,B,NACT]
    const float* __restrict__ W1,       // [NA,H,H]
    const float* __restrict__ b1,       // [NA,H]
    const float* __restrict__ W2,       // [NA,H,NACT]
    const float* __restrict__ b2,       // [NA,NACT]
    float* __restrict__ qout)           // [NA,B,1]
{
    extern __shared__ char smem_raw[];
    SmemB& s = *reinterpret_cast<SmemB*>(smem_raw);

    const int tid  = threadIdx.x;
    const int b    = blockIdx.x;
    const int lane = tid & 31;
    const int w    = tid >> 5;

    // ---- load u[b] (2048 floats, coalesced) ----
    const float* ub = unary + (size_t)b * (N_ * F_);
    #pragma unroll
    for (int p = 0; p < 8; ++p) {
        int li = tid + p * 256;
        s.ov.p1.u[li >> 6][li & 63] = ub[li];
    }
    s.m[tid] = 0u;
    __syncthreads();

    // ---- binary[b] (8192 ints, int4-coalesced) -> bitmasks ----
    const int4* bb = reinterpret_cast<const int4*>(binary + (size_t)b * (N_ * N_ * E_));
    #pragma unroll
    for (int p = 0; p < 8; ++p) {
        int q4 = tid + p * 256;
        int4 v = bb[q4];
        int l  = q4 * 4;              // linear index (i*32 + j)*8 + e
        int i  = l >> 8;
        int j  = (l >> 3) & 31;
        int e0 = l & 7;               // 0 or 4
        unsigned bit = 1u << i;
        if (v.x) atomicOr(&s.m[(e0 + 0) * 32 + j], bit);
        if (v.y) atomicOr(&s.m[(e0 + 1) * 32 + j], bit);
        if (v.z) atomicOr(&s.m[(e0 + 2) * 32 + j], bit);
        if (v.w) atomicOr(&s.m[(e0 + 3) * 32 + j], bit);
    }
    __syncthreads();
    {
        int d = __popc(s.m[tid]);
        s.ov.p1.cinv[tid] = d ? (1.0f / (float)d) : 0.0f;
    }
    __syncthreads();

    // ========================================================================
    // Aggregation: thread = (d-group = warp, node j = lane).
    // Read u[i][8 floats] ONCE per i (broadcast LDS.128), apply to all 8
    // relations via bitmask-predicated adds. Lane j captures the broadcast at
    // i == lane to get its root-term row for free (no column reads of u).
    // Writes ubarT rows 0..511 (aggregated) and 512..575 (root).
    // ========================================================================
    {
        const int d0 = w * 8;   // this warp's 8 d-values
        unsigned mk[E_];
        float    ci[E_];
        #pragma unroll
        for (int e = 0; e < E_; ++e) {
            mk[e] = s.m[e * 32 + lane];
            ci[e] = s.ov.p1.cinv[e * 32 + lane];
        }
        float a8[E_][8];
        #pragma unroll
        for (int e = 0; e < E_; ++e)
            #pragma unroll
            for (int d = 0; d < 8; ++d) a8[e][d] = 0.0f;
        float root8[8];

        #pragma unroll 4
        for (int i = 0; i < N_; ++i) {
            float4 ua  = *reinterpret_cast<const float4*>(&s.ov.p1.u[i][d0]);
            float4 ubv = *reinterpret_cast<const float4*>(&s.ov.p1.u[i][d0 + 4]);
            if (i == lane) {   // capture own row for root term
                root8[0] = ua.x;  root8[1] = ua.y;
                root8[2] = ua.z;  root8[3] = ua.w;
                root8[4] = ubv.x; root8[5] = ubv.y;
                root8[6] = ubv.z; root8[7] = ubv.w;
            }
            #pragma unroll
            for (int e = 0; e < E_; ++e) {
                if ((mk[e] >> i) & 1u) {
                    a8[e][0] += ua.x;  a8[e][1] += ua.y;
                    a8[e][2] += ua.z;  a8[e][3] += ua.w;
                    a8[e][4] += ubv.x; a8[e][5] += ubv.y;
                    a8[e][6] += ubv.z; a8[e][7] += ubv.w;
                }
            }
        }
        #pragma unroll
        for (int e = 0; e < E_; ++e)
            #pragma unroll
            for (int d = 0; d < 8; ++d)
                s.ubarT[e * 64 + d0 + d][lane] = a8[e][d] * ci[e];

        // root fold: ubarT[512 + d0 + d][j] = u[j][d0 + d]
        #pragma unroll
        for (int d = 0; d < 8; ++d)
            s.ubarT[512 + d0 + d][lane] = root8[d];
    }
    __syncthreads();   // ubarT complete; u/cinv now dead (wtile reuses region)

    // ========================================================================
    // GEMM: h[j][c] = sum_k ubarT[k][j] * Wcat[k][c], k = 0..575.
    // Thread: 4 consecutive nodes x 4 consecutive cols (16 acc).
    //   nodes nj..nj+3 with nj = (lane&7)*4; cols cg*4 with cg = w*4 + (lane>>3).
    // Per k: 1 LDS.128 act + 1 LDS.128 wt + 16 FMA.
    // ========================================================================
    const int nj = (lane & 7) * 4;
    const int cg = w * 4 + (lane >> 3);

    float acc[4][4];
    #pragma unroll
    for (int n = 0; n < 4; ++n)
        #pragma unroll
        for (int c = 0; c < 4; ++c) acc[n][c] = 0.0f;

    for (int t = 0; t < 9; ++t) {
        // stage 64-row Wcat tile (coalesced float4)
        {
            const float4* src = reinterpret_cast<const float4*>(g_Wcat + (t * 64) * H_);
            float4*       dst = reinterpret_cast<float4*>(&s.ov.wtile[0][0]);
            #pragma unroll
            for (int p = 0; p < 8; ++p)
                dst[tid + p * 256] = src[tid + p * 256];
        }
        __syncthreads();
        #pragma unroll 8
        for (int k = 0; k < 64; ++k) {
            float4 av = *reinterpret_cast<const float4*>(&s.ubarT[t * 64 + k][nj]);
            float4 wv = *reinterpret_cast<const float4*>(&s.ov.wtile[k][cg * 4]);
            acc[0][0] = fmaf(av.x, wv.x, acc[0][0]);
            acc[0][1] = fmaf(av.x, wv.y, acc[0][1]);
            acc[0][2] = fmaf(av.x, wv.z, acc[0][2]);
            acc[0][3] = fmaf(av.x, wv.w, acc[0][3]);
            acc[1][0] = fmaf(av.y, wv.x, acc[1][0]);
            acc[1][1] = fmaf(av.y, wv.y, acc[1][1]);
            acc[1][2] = fmaf(av.y, wv.z, acc[1][2]);
            acc[1][3] = fmaf(av.y, wv.w, acc[1][3]);
            acc[2][0] = fmaf(av.z, wv.x, acc[2][0]);
            acc[2][1] = fmaf(av.z, wv.y, acc[2][1]);
            acc[2][2] = fmaf(av.z, wv.z, acc[2][2]);
            acc[2][3] = fmaf(av.z, wv.w, acc[2][3]);
            acc[3][0] = fmaf(av.w, wv.x, acc[3][0]);
            acc[3][1] = fmaf(av.w, wv.y, acc[3][1]);
            acc[3][2] = fmaf(av.w, wv.z, acc[3][2]);
            acc[3][3] = fmaf(av.w, wv.w, acc[3][3]);
        }
        __syncthreads();
    }

    // ---- mask-bias rows 576..583 + constant bias row 584 (direct L2) ----
    #pragma unroll
    for (int e = 0; e < E_; ++e) {
        float4 wv = __ldg(reinterpret_cast<const float4*>(
                          g_Wcat + (576 + e) * H_ + cg * 4));
        #pragma unroll
        for (int n = 0; n < 4; ++n) {
            if (s.m[e * 32 + nj + n]) {
                acc[n][0] += wv.x; acc[n][1] += wv.y;
                acc[n][2] += wv.z; acc[n][3] += wv.w;
            }
        }
    }
    {
        float4 wv = __ldg(reinterpret_cast<const float4*>(
                          g_Wcat + 584 * H_ + cg * 4));
        #pragma unroll
        for (int n = 0; n < 4; ++n) {
            acc[n][0] += wv.x; acc[n][1] += wv.y;
            acc[n][2] += wv.z; acc[n][3] += wv.w;
        }
    }

    // ---- relu + max-pool over nodes ----
    // per-thread max over its 4 nodes, then xor-shfl over the 8 node-groups
    // (lane bits 0..2), leaving pooled value replicated in each 8-lane group.
    #pragma unroll
    for (int c = 0; c < 4; ++c) {
        float v = fmaxf(fmaxf(fmaxf(acc[0][c], acc[1][c]),
                              fmaxf(acc[2][c], acc[3][c])), 0.0f);
        v = fmaxf(v, __shfl_xor_sync(0xffffffffu, v, 1));
        v = fmaxf(v, __shfl_xor_sync(0xffffffffu, v, 2));
        v = fmaxf(v, __shfl_xor_sync(0xffffffffu, v, 4));
        if ((lane & 7) == 0) s.pooled[cg * 4 + c] = v;
    }
    __syncthreads();

    // ---- per-agent heads: z = leaky(pooled@W1 + b1); q = z@W2[:,argmax] + b2 ----
    if (tid < NA_) {
        const float* ap = actions + ((size_t)tid * B_ + b) * NACT_;
        float best = ap[0]; int col = 0;
        #pragma unroll
        for (int k = 1; k < NACT_; ++k) {
            float v = ap[k];
            if (v > best) { best = v; col = k; }
        }
        s.cols[tid] = col;
    }
    {
        int a  = tid >> 6;       // agent
        int hh = tid & 63;
        #pragma unroll
        for (int rep = 0; rep < 2; ++rep) {
            int h = hh + rep * 64;
            float z = b1[a * H_ + h];
            const float* w1p = W1 + a * H_ * H_ + h;
            #pragma unroll 8
            for (int t = 0; t < H_; ++t)
                z = fmaf(s.pooled[t], __ldg(w1p + t * H_), z);
            z = (z > 0.0f) ? z : 0.01f * z;   // LeakyReLU
            s.zs[a][h] = z;
        }
    }
    __syncthreads();
    if (tid < NA_) {
        int a = tid;
        int col = s.cols[a];
        float q = b2[a * NACT_ + col];
        const float* w2p = W2 + a * H_ * NACT_ + col;
        #pragma unroll 8
        for (int h = 0; h < H_; ++h)
            q = fmaf(s.zs[a][h], __ldg(w2p + h * NACT_), q);
        qout[(size_t)a * B_ + b] = q;
    }
}

// ---------------------------------------------------------------------------
extern "C" void kernel_launch(void* const* d_in, const int* in_sizes, int n_in,
                              void* d_out, int out_size) {
    const float* unary   = (const float*)d_in[0];
    const int*   binary  = (const int*)  d_in[1];
    const float* actions = (const float*)d_in[2];
    const float* We      = (const float*)d_in[3];
    const float* be      = (const float*)d_in[4];
    const float* Wrel    = (const float*)d_in[5];
    const float* Wroot   = (const float*)d_in[6];
    const float* brel    = (const float*)d_in[7];
    const float* W1      = (const float*)d_in[8];
    const float* b1      = (const float*)d_in[9];
    const float* W2      = (const float*)d_in[10];
    const float* b2      = (const float*)d_in[11];
    float* qout = (float*)d_out;

    cudaFuncSetAttribute(critic_main, cudaFuncAttributeMaxDynamicSharedMemorySize,
                         (int)sizeof(SmemB));

    precompute_wcat<<<K_TOT, H_>>>(We, be, Wrel, Wroot, brel);
    critic_main<<<B_, 256, sizeof(SmemB)>>>(unary, binary, actions, W1, b1, W2, b2, qout);
}